// round 8
// baseline (speedup 1.0000x reference)
#include <cuda_runtime.h>
#include <cstdint>

// SplineActivation: y[b,w] = clamped cubic B-spline (16 uniform knots on [-3,3],
// degree 3) of x[b,w], per-channel coefficients coefs[w, 0..17].
//
// Round-8 (= round-7 theory, compile fix): R4/R6 pinned at 16.77us across
// MLP/occupancy changes -> structural LSU floor; largest line item = STG.32
// (5 cyc issue each). Keep the proven conflict-free scalar-channel compute and
// replace per-thread global stores with double-buffered smem staging (STS.32,
// 1 wavefront) + cp.async.bulk 512B-per-row TMA stores issued by 16 threads,
// 2 bulk groups deep.

#define W_TOTAL  1024
#define B_TOTAL  8192
#define NB_IV    15
#define CH       128
#define BD       256
#define R        8            // rows per thread per iteration (16 rows/CTA-iter)
#define N_CTRL   18
#define GY       74           // 8 x 74 = 592 CTAs = 4 per SM

__device__ float4 g_poly[NB_IV * W_TOTAL];   // [interval][channel] monomial cubic

// ---------------------------------------------------------------------------
// Fused build (unchanged): 15x4 conversion cubics in smem, one g_poly entry
// per thread. Grid 60 x 256.
// ---------------------------------------------------------------------------
__global__ __launch_bounds__(BD)
void build_poly_kernel(const float* __restrict__ coefs) {
    __shared__ float4 M[NB_IV * 4];
    const int t = threadIdx.x;

    if (t < NB_IV * 4) {
        const int k = t >> 2;
        const int j = t & 3;

        float tk[22];
#pragma unroll
        for (int m = 0; m < 16; m++)
            tk[3 + m] = (float)(-3.0 + (double)m * (6.0 / 15.0));
        tk[0] = tk[1] = tk[2] = tk[3];
        tk[19] = tk[20] = tk[21] = tk[18];

        const int   kg    = k + 3;
        const float x0    = tk[kg];
        const float delta = (tk[kg + 1] - tk[kg]) * (1.0f / 3.0f);
        const float Kev   = fmaf((float)k, 0.4f, -3.0f);

        float f[4];
#pragma unroll
        for (int m = 0; m < 4; m++) {
            float x = x0 + delta * (float)m;
            float left[3], right[3];
#pragma unroll
            for (int i2 = 1; i2 <= 3; i2++) {
                left [i2 - 1] = x - tk[kg + 1 - i2];
                right[i2 - 1] = tk[kg + i2] - x;
            }
            float N[4];
            N[0] = 1.0f;
#pragma unroll
            for (int jj = 1; jj <= 3; jj++) {
                float saved = 0.0f;
#pragma unroll
                for (int r = 0; r < jj; r++) {
                    float temp = N[r] / (right[r] + left[jj - 1 - r]);
                    N[r] = saved + right[r] * temp;
                    saved = left[jj - 1 - r] * temp;
                }
                N[jj] = saved;
            }
            f[m] = N[j];
        }

        const float id = 1.0f / delta;
        const float d1 = (f[1] - f[0]) * id;
        const float d2 = (f[2] - 2.0f * f[1] + f[0]) * (0.5f * id * id);
        const float d3 = (f[3] - 3.0f * f[2] + 3.0f * f[1] - f[0])
                         * ((1.0f / 6.0f) * id * id * id);
        const float a0 = f[0];
        const float a1 = d1 - delta * d2 + 2.0f * delta * delta * d3;
        const float a2 = d2 - 3.0f * delta * d3;
        const float a3 = d3;

        const float s0 = x0 - Kev;
        const float b3 = a3;
        const float b2 = a2 - 3.0f * a3 * s0;
        const float b1 = a1 - 2.0f * a2 * s0 + 3.0f * a3 * s0 * s0;
        const float b0 = a0 - a1 * s0 + a2 * s0 * s0 - a3 * s0 * s0 * s0;

        M[t] = make_float4(b0, b1, b2, b3);
    }
    __syncthreads();

    const int idx = blockIdx.x * BD + t;
    const int c   = idx & (W_TOTAL - 1);
    const int k   = idx >> 10;

    float4 acc = make_float4(0.f, 0.f, 0.f, 0.f);
#pragma unroll
    for (int j = 0; j < 4; j++) {
        float  cf = __ldg(&coefs[c * N_CTRL + k + j]);
        float4 m  = M[k * 4 + j];
        acc.x = fmaf(cf, m.x, acc.x);
        acc.y = fmaf(cf, m.y, acc.y);
        acc.z = fmaf(cf, m.z, acc.z);
        acc.w = fmaf(cf, m.w, acc.w);
    }
    g_poly[k * W_TOTAL + c] = acc;
}

// ---------------------------------------------------------------------------
// Hot kernel. Compute identical to R6 (conflict-free LDS.128 gather). Output:
// STS.32 into ybuf[2][16][128] (lane = ch -> 1 wavefront), then 16 threads
// issue one 512B cp.async.bulk store per row; 2 bulk groups in flight.
// ---------------------------------------------------------------------------
__global__ __launch_bounds__(BD, 4)
void spline_eval_kernel(const float* __restrict__ X, float* __restrict__ Y) {
    __shared__ float4 sp[NB_IV][CH];            // 30,720 B
    __shared__ __align__(16) float ybuf[2][2 * R][CH];  // 16,384 B
    const int t  = threadIdx.x;
    const int c0 = blockIdx.x * CH;

    for (int i = t; i < NB_IV * CH; i += BD)
        ((float4*)sp)[i] = g_poly[(i >> 7) * W_TOTAL + c0 + (i & (CH - 1))];
    __syncthreads();

    const int ch = t & (CH - 1);
    const int rl = t >> 7;                      // 0..1
    const int rstep = gridDim.y * 2 * R;

    int it = 0;
    for (int base = blockIdx.y * 2 * R; base < B_TOTAL; base += rstep, it++) {
        const int buf = it & 1;
        const int r0  = base + rl * R;          // this thread: rows r0 .. r0+7
        const float* xp = X + (size_t)r0 * W_TOTAL + c0 + ch;

        float xv[R];
#pragma unroll
        for (int q = 0; q < R; q++) xv[q] = xp[q * W_TOTAL];

#pragma unroll
        for (int q = 0; q < R; q++) {
            float x  = xv[q];
            float fi = floorf(fmaf(x, 2.5f, 7.5f));
            fi       = fminf(fmaxf(fi, 0.0f), 14.0f);
            int   k  = (int)fi;
            float s  = x - fmaf(fi, 0.4f, -3.0f);
            float4 p = sp[k][ch];
            xv[q] = fmaf(fmaf(fmaf(p.w, s, p.z), s, p.y), s, p.x);
        }

        // Make sure the bulk-store group that last read this buffer is done.
        if (t < 2 * R)
            asm volatile("cp.async.bulk.wait_group 1;" ::: "memory");
        __syncthreads();

#pragma unroll
        for (int q = 0; q < R; q++)
            ybuf[buf][rl * R + q][ch] = xv[q];
        __syncthreads();

        if (t < 2 * R) {
            asm volatile("fence.proxy.async.shared::cta;" ::: "memory");
            unsigned int saddr;
            asm("{ .reg .u64 a; cvta.to.shared.u64 a, %1; cvt.u32.u64 %0, a; }"
                : "=r"(saddr) : "l"(&ybuf[buf][t][0]));
            float* gdst = Y + (size_t)(base + t) * W_TOTAL + c0;
            asm volatile(
                "cp.async.bulk.global.shared::cta.bulk_group [%0], [%1], %2;"
                :: "l"(gdst), "r"(saddr), "n"(CH * 4) : "memory");
            asm volatile("cp.async.bulk.commit_group;" ::: "memory");
        }
    }

    if (t < 2 * R)
        asm volatile("cp.async.bulk.wait_group 0;" ::: "memory");
}

// ---------------------------------------------------------------------------
extern "C" void kernel_launch(void* const* d_in, const int* in_sizes, int n_in,
                              void* d_out, int out_size) {
    const float* X     = (const float*)d_in[0];
    const float* coefs = (const float*)d_in[1];
    if (n_in >= 2 && in_sizes[0] < in_sizes[1]) {   // identify by size
        X     = (const float*)d_in[1];
        coefs = (const float*)d_in[0];
    }
    float* Y = (float*)d_out;

    build_poly_kernel<<<NB_IV * W_TOTAL / BD, BD>>>(coefs);   // 60 x 256

    dim3 grid(W_TOTAL / CH, GY);               // 8 x 74 = 592 = 4 per SM
    spline_eval_kernel<<<grid, BD>>>(X, Y);
}